// round 15
// baseline (speedup 1.0000x reference)
#include <cuda_runtime.h>
#include <math.h>

#define DIM_EI  4096
#define DIM_CA3 8192
#define DIM_CA1 8192
#define DIM_EO  4096

static constexpr float BETA  = 10.0f;
static constexpr float ALPHA = 0.01f;

// ---------------- device scratch ----------------
__device__ float g_h1[DIM_CA3];
__device__ float g_h3[DIM_CA1];
__device__ float g_h4[DIM_EO];
__device__ float g_xca3[DIM_CA3];
__device__ float g_IS[DIM_CA1];
__device__ float g_xca1[DIM_CA1];
__device__ int   g_nnz_idx[DIM_CA3];
__device__ float g_nnz_val[DIM_CA3];
__device__ int   g_nnz_cnt;
__device__ int   g_act_idx[DIM_CA1];   // rows with IS > 0
__device__ int   g_act_cnt;
__device__ unsigned g_ctr;

// ---------------- helpers ----------------
__device__ __forceinline__ unsigned f2u(float f) {
    unsigned u = __float_as_uint(f);
    return (u & 0x80000000u) ? ~u : (u | 0x80000000u);
}
__device__ __forceinline__ float u2f(unsigned u) {
    return __uint_as_float((u & 0x80000000u) ? (u & 0x7fffffffu) : ~u);
}
__device__ __forceinline__ float sigm(float z) { return 1.0f / (1.0f + expf(-z)); }
__device__ __forceinline__ float dot4(float4 a, float4 b) {
    return a.x * b.x + a.y * b.y + a.z * b.z + a.w * b.w;
}

// Block reduction (256 threads) -> result valid on thread 0.
__device__ __forceinline__ float block_reduce_256(float v) {
    __shared__ float sp[8];
    int lane = threadIdx.x & 31, wid = threadIdx.x >> 5;
    #pragma unroll
    for (int o = 16; o; o >>= 1) v += __shfl_down_sync(0xffffffffu, v, o);
    if (lane == 0) sp[wid] = v;
    __syncthreads();
    if (threadIdx.x < 32) {
        v = (lane < 8) ? sp[lane] : 0.0f;
        #pragma unroll
        for (int o = 4; o; o >>= 1) v += __shfl_down_sync(0xffffffffu, v, o);
    }
    return v;
}

// Warp-aggregated histogram add (conflict-free for hot bins).
__device__ __forceinline__ void hist_add(unsigned* s_hist, int bin, bool pred) {
    unsigned active = __ballot_sync(0xffffffffu, pred);
    if (pred) {
        unsigned mask = __match_any_sync(active, bin);
        int leader = __ffs(mask) - 1;
        if ((int)(threadIdx.x & 31) == leader)
            atomicAdd(&s_hist[bin], (unsigned)__popc(mask));
    }
}

// Warp 0 locates the bin holding the k-th largest in a 256-bin histogram.
__device__ __forceinline__ void find_bin_warp0(const unsigned* s_hist, int k,
                                               int* s_bin, int* s_k) {
    if (threadIdx.x < 32) {
        int lane = threadIdx.x;
        unsigned b[8]; unsigned tot = 0;
        #pragma unroll
        for (int j = 0; j < 8; j++) { b[j] = s_hist[lane * 8 + j]; tot += b[j]; }
        unsigned suf = tot;
        #pragma unroll
        for (int o = 1; o < 32; o <<= 1) {
            unsigned n = __shfl_down_sync(0xffffffffu, suf, o);
            if (lane + o < 32) suf += n;
        }
        unsigned above = suf - tot;
        unsigned ge[8]; unsigned run = above;
        #pragma unroll
        for (int j = 7; j >= 0; j--) { run += b[j]; ge[j] = run; }
        unsigned gt = above;
        #pragma unroll
        for (int j = 7; j >= 0; j--) {
            if (ge[j] >= (unsigned)k && gt < (unsigned)k) {
                *s_bin = lane * 8 + j;
                *s_k   = k - (int)gt;
            }
            gt = ge[j];
        }
    }
}

// Exact K-th largest via candidate compaction (pass 1 full, passes 2-4 over
// the ~candidates sharing the selected top byte). Fallback: full passes.
template<int M>
__device__ float kth_select(const unsigned* uv, int K) {
    __shared__ unsigned s_hist[256];
    __shared__ unsigned s_cand[2048];
    __shared__ int s_bin, s_k, s_cnt;
    if (threadIdx.x < 256) s_hist[threadIdx.x] = 0;
    __syncthreads();
    #pragma unroll
    for (int j = 0; j < M; j++) hist_add(s_hist, uv[j] >> 24, true);
    __syncthreads();
    find_bin_warp0(s_hist, K, &s_bin, &s_k);
    __syncthreads();
    unsigned b0 = (unsigned)s_bin;
    int k = s_k;
    unsigned prefix = b0 << 24;
    if (threadIdx.x == 0) s_cnt = 0;
    __syncthreads();
    #pragma unroll
    for (int j = 0; j < M; j++) {
        if ((uv[j] >> 24) == b0) {
            int pos = atomicAdd(&s_cnt, 1);
            if (pos < 2048) s_cand[pos] = uv[j];
        }
    }
    __syncthreads();
    int cnt = s_cnt;
    if (cnt <= 2048) {
        #pragma unroll
        for (int shift = 16; shift >= 0; shift -= 8) {
            unsigned hi = 0xFFFFFFFFu << (shift + 8);
            if (threadIdx.x < 256) s_hist[threadIdx.x] = 0;
            __syncthreads();
            for (int i = threadIdx.x; i < cnt; i += blockDim.x) {
                unsigned u = s_cand[i];
                if ((u & hi) == prefix) atomicAdd(&s_hist[(u >> shift) & 255], 1u);
            }
            __syncthreads();
            find_bin_warp0(s_hist, k, &s_bin, &s_k);
            __syncthreads();
            prefix |= ((unsigned)s_bin) << shift;
            k = s_k;
            __syncthreads();
        }
        return u2f(prefix);
    }
    #pragma unroll
    for (int shift = 16; shift >= 0; shift -= 8) {
        unsigned hi = 0xFFFFFFFFu << (shift + 8);
        if (threadIdx.x < 256) s_hist[threadIdx.x] = 0;
        __syncthreads();
        #pragma unroll
        for (int j = 0; j < M; j++) {
            unsigned u = uv[j];
            hist_add(s_hist, (u >> shift) & 255, (u & hi) == prefix);
        }
        __syncthreads();
        find_bin_warp0(s_hist, k, &s_bin, &s_k);
        __syncthreads();
        prefix |= ((unsigned)s_bin) << shift;
        k = s_k;
        __syncthreads();
    }
    return u2f(prefix);
}

// ---------------- K1: dual matvec, BLOCK-per-row (grid 16384, R13 winner) -------------
__global__ __launch_bounds__(256) void matvec_dual_kernel(
        const float* __restrict__ Wa, const float* __restrict__ Wb,
        const float* __restrict__ x) {
    int r = blockIdx.x;
    const float* W; float* out;
    if (r < DIM_CA3) { W = Wa; out = g_h1; }
    else             { W = Wb; out = g_h3; r -= DIM_CA3; }
    const float4* w4 = reinterpret_cast<const float4*>(W) + (size_t)r * (DIM_EI / 4);
    const float4* x4 = reinterpret_cast<const float4*>(x);
    int t = threadIdx.x;
    float4 a0 = __ldcs(&w4[t]);
    float4 a1 = __ldcs(&w4[t + 256]);
    float4 a2 = __ldcs(&w4[t + 512]);
    float4 a3 = __ldcs(&w4[t + 768]);
    float4 b0 = __ldg(&x4[t]);
    float4 b1 = __ldg(&x4[t + 256]);
    float4 b2 = __ldg(&x4[t + 512]);
    float4 b3 = __ldg(&x4[t + 768]);
    float acc = dot4(a0, b0) + dot4(a1, b1) + dot4(a2, b2) + dot4(a3, b3);
    float sum = block_reduce_256(acc);
    if (threadIdx.x == 0) out[r] = sum;
}

// ---------------- K2: block0 -> top-2(h1)+x_ca3+nnz; block1 -> top-100(h3)+IS+act -----
__global__ void stageA_kernel() {
    __shared__ int wsum[32];
    int lane = threadIdx.x & 31, wid = threadIdx.x >> 5;
    int base = threadIdx.x * 8;
    const float* src = (blockIdx.x == 0) ? g_h1 : g_h3;
    int K = (blockIdx.x == 0) ? 2 : 100;

    float xv[8]; unsigned uv[8];
    #pragma unroll
    for (int j = 0; j < 8; j++) { xv[j] = src[base + j]; uv[j] = f2u(xv[j]); }
    float th = kth_select<8>(uv, K);

    float vals[8]; int keep[8]; int cnt = 0;
    #pragma unroll
    for (int j = 0; j < 8; j++) {
        int kp = (xv[j] >= th);
        float v = kp ? sigm(BETA * (xv[j] - th)) : 0.0f;
        vals[j] = v; keep[j] = kp; cnt += kp;
        if (blockIdx.x == 0) g_xca3[base + j] = v;
        else                 g_IS[base + j]   = v;
    }
    // deterministic ordered compaction
    int incl = cnt;
    #pragma unroll
    for (int o = 1; o < 32; o <<= 1) {
        int n = __shfl_up_sync(0xffffffffu, incl, o);
        if (lane >= o) incl += n;
    }
    if (lane == 31) wsum[wid] = incl;
    __syncthreads();
    if (threadIdx.x == 0) {
        int s = 0;
        #pragma unroll
        for (int i = 0; i < 32; i++) { int c = wsum[i]; wsum[i] = s; s += c; }
        if (blockIdx.x == 0) { g_nnz_cnt = s; g_ctr = 0; }
        else                 { g_act_cnt = s; }
    }
    __syncthreads();
    int off = wsum[wid] + incl - cnt;
    if (blockIdx.x == 0) {
        #pragma unroll
        for (int j = 0; j < 8; j++)
            if (keep[j]) { g_nnz_idx[off] = base + j; g_nnz_val[off] = vals[j]; ++off; }
    } else {
        #pragma unroll
        for (int j = 0; j < 8; j++)
            if (keep[j]) { g_act_idx[off] = base + j; ++off; }
    }
}

// ---------------- copy_W: out_W = W (no dependencies; fills stageA bubble) ------------
__global__ void copy_W_kernel(const float* __restrict__ W, float* __restrict__ out) {
    size_t idx = ((size_t)blockIdx.x * blockDim.x + threadIdx.x) * 8;
    float4 w0 = __ldcs(reinterpret_cast<const float4*>(W + idx));
    float4 w1 = __ldcs(reinterpret_cast<const float4*>(W + idx + 4));
    __stcs(reinterpret_cast<float4*>(out + idx), w0);
    __stcs(reinterpret_cast<float4*>(out + idx + 4), w1);
}

// ---------------- fixup: rewrite the ~100 rows with IS > 0 ----------------------------
__global__ void fixup_W_kernel(const float* __restrict__ W, float* __restrict__ out) {
    int nact = g_act_cnt;
    for (int a = blockIdx.x; a < nact; a += gridDim.x) {
        int row = g_act_idx[a];
        float s = g_IS[row];
        float ca = 1.0f - s * ALPHA;
        float cb = ALPHA * s;
        const float4* w4  = reinterpret_cast<const float4*>(W)   + (size_t)row * (DIM_CA3 / 4);
        float4*       o4  = reinterpret_cast<float4*>(out)       + (size_t)row * (DIM_CA3 / 4);
        const float4* xc4 = reinterpret_cast<const float4*>(g_xca3);
        for (int j = threadIdx.x; j < DIM_CA3 / 4; j += blockDim.x) {
            float4 w = w4[j], xc = xc4[j];
            float4 o;
            o.x = ca * w.x + cb * xc.x;
            o.y = ca * w.y + cb * xc.y;
            o.z = ca * w.z + cb * xc.z;
            o.w = ca * w.w + cb * xc.w;
            o4[j] = o;
        }
    }
}

// ---------------- K3: fused h2 gather (~2 nnz) + top-100 + dense sigmoid --------------
__global__ void stageBC_kernel(const float* __restrict__ W3) {
    int cnt = g_nnz_cnt;
    int base = threadIdx.x * 8;
    float hv[8]; unsigned uv[8];
    #pragma unroll
    for (int r = 0; r < 8; r++) {
        size_t rowoff = (size_t)(base + r) * DIM_CA3;
        float acc = 0.0f;
        for (int k = 0; k < cnt; k++)
            acc += W3[rowoff + g_nnz_idx[k]] * g_nnz_val[k];
        hv[r] = acc; uv[r] = f2u(acc);
    }
    float th = kth_select<8>(uv, 100);
    #pragma unroll
    for (int r = 0; r < 8; r++)
        g_xca1[base + r] = sigm(BETA * (hv[r] - th));   // flag=False: no hard mask
}

// ---------------- K5: matvec_out BLOCK-per-row (grid 4096) + fused top-50 tail --------
__global__ __launch_bounds__(256) void matvec_out_kernel(
        const float* __restrict__ W, float* __restrict__ out) {
    int r = blockIdx.x;
    int tid = threadIdx.x;
    const float4* w4 = reinterpret_cast<const float4*>(W) + (size_t)r * (DIM_CA1 / 4);
    const float4* x4 = reinterpret_cast<const float4*>(g_xca1);
    float acc = 0.0f;
    float4 a0 = __ldcs(&w4[tid]);
    float4 a1 = __ldcs(&w4[tid + 256]);
    float4 a2 = __ldcs(&w4[tid + 512]);
    float4 a3 = __ldcs(&w4[tid + 768]);
    float4 a4 = __ldcs(&w4[tid + 1024]);
    float4 a5 = __ldcs(&w4[tid + 1280]);
    float4 a6 = __ldcs(&w4[tid + 1536]);
    float4 a7 = __ldcs(&w4[tid + 1792]);
    acc += dot4(a0, __ldg(&x4[tid]));
    acc += dot4(a1, __ldg(&x4[tid + 256]));
    acc += dot4(a2, __ldg(&x4[tid + 512]));
    acc += dot4(a3, __ldg(&x4[tid + 768]));
    acc += dot4(a4, __ldg(&x4[tid + 1024]));
    acc += dot4(a5, __ldg(&x4[tid + 1280]));
    acc += dot4(a6, __ldg(&x4[tid + 1536]));
    acc += dot4(a7, __ldg(&x4[tid + 1792]));
    float sum = block_reduce_256(acc);
    if (tid == 0) {
        g_h4[r] = sum;
        __threadfence();
    }
    __syncthreads();
    __shared__ bool s_last;
    if (tid == 0) {
        unsigned t = atomicAdd(&g_ctr, 1u);
        s_last = (t == gridDim.x - 1);
    }
    __syncthreads();
    if (!s_last) return;
    __threadfence();
    unsigned uv[16];
    #pragma unroll
    for (int j = 0; j < 16; j++) uv[j] = f2u(g_h4[tid * 16 + j]);
    float th = kth_select<16>(uv, 50);
    for (int i = tid; i < DIM_EO; i += 256) {
        float xx = g_h4[i];
        out[i] = (xx >= th) ? sigm(BETA * (xx - th)) : 0.0f;
    }
}

// ---------------- launch ----------------
// s0: mv_dual [e_mv] -> stageA [e_A] -> wait(e_copy) -> fixup -> wait(e_out)
// s1: wait(e_mv) -> copy_W [e_copy]          (536 MB, hides stageA + B-chain)
// s2: wait(e_A)  -> stageBC -> matvec_out [e_out]
extern "C" void kernel_launch(void* const* d_in, const int* in_sizes, int n_in,
                              void* d_out, int out_size) {
    const float* x_ei      = (const float*)d_in[0];
    const float* W_ei_ca3  = (const float*)d_in[1];
    const float* W_ei_ca1  = (const float*)d_in[2];
    const float* W_ca3_ca1 = (const float*)d_in[3];
    const float* W_ca1_eo  = (const float*)d_in[4];
    float* out = (float*)d_out;

    cudaStream_t s1, s2;
    cudaStreamCreateWithFlags(&s1, cudaStreamNonBlocking);
    cudaStreamCreateWithFlags(&s2, cudaStreamNonBlocking);
    cudaEvent_t e_mv, e_A, e_copy, e_out;
    cudaEventCreateWithFlags(&e_mv,   cudaEventDisableTiming);
    cudaEventCreateWithFlags(&e_A,    cudaEventDisableTiming);
    cudaEventCreateWithFlags(&e_copy, cudaEventDisableTiming);
    cudaEventCreateWithFlags(&e_out,  cudaEventDisableTiming);

    matvec_dual_kernel<<<DIM_CA3 + DIM_CA1, 256>>>(W_ei_ca3, W_ei_ca1, x_ei);
    cudaEventRecord(e_mv, 0);
    stageA_kernel<<<2, 1024>>>();
    cudaEventRecord(e_A, 0);

    // s1: speculative copy (no data deps) — keeps DRAM busy during stageA
    cudaStreamWaitEvent(s1, e_mv, 0);
    copy_W_kernel<<<(unsigned)((size_t)DIM_CA1 * DIM_CA3 / 8 / 256), 256, 0, s1>>>(
        W_ca3_ca1, out + DIM_EO);
    cudaEventRecord(e_copy, s1);

    // s2: B-chain, hidden under the copy
    cudaStreamWaitEvent(s2, e_A, 0);
    stageBC_kernel<<<1, 1024, 0, s2>>>(W_ca3_ca1);
    matvec_out_kernel<<<DIM_EO, 256, 0, s2>>>(W_ca1_eo, out);
    cudaEventRecord(e_out, s2);

    // s0: fixup after copy (stageA already ordered in-stream)
    cudaStreamWaitEvent(0, e_copy, 0);
    fixup_W_kernel<<<128, 256>>>(W_ca3_ca1, out + DIM_EO);
    cudaStreamWaitEvent(0, e_out, 0);

    cudaEventDestroy(e_mv);
    cudaEventDestroy(e_A);
    cudaEventDestroy(e_copy);
    cudaEventDestroy(e_out);
    cudaStreamDestroy(s1);
    cudaStreamDestroy(s2);
}

// round 16
// speedup vs baseline: 1.0447x; 1.0447x over previous
#include <cuda_runtime.h>
#include <math.h>

#define DIM_EI  4096
#define DIM_CA3 8192
#define DIM_CA1 8192
#define DIM_EO  4096
#define NROWS   (DIM_CA3 + DIM_CA1)

static constexpr float BETA  = 10.0f;
static constexpr float ALPHA = 0.01f;

// ---------------- device scratch ----------------
__device__ float g_hp0[NROWS];        // partial dot (first half of row)
__device__ float g_hp1[NROWS];        // partial dot (second half of row)
__device__ float g_h4[DIM_EO];
__device__ float g_xca3[DIM_CA3];
__device__ float g_IS[DIM_CA1];
__device__ float g_xca1[DIM_CA1];
__device__ int   g_nnz_idx[DIM_CA3];
__device__ float g_nnz_val[DIM_CA3];
__device__ int   g_nnz_cnt;
__device__ unsigned g_ctr;

// ---------------- helpers ----------------
__device__ __forceinline__ unsigned f2u(float f) {
    unsigned u = __float_as_uint(f);
    return (u & 0x80000000u) ? ~u : (u | 0x80000000u);
}
__device__ __forceinline__ float u2f(unsigned u) {
    return __uint_as_float((u & 0x80000000u) ? (u & 0x7fffffffu) : ~u);
}
__device__ __forceinline__ float sigm(float z) { return 1.0f / (1.0f + expf(-z)); }
__device__ __forceinline__ float dot4(float4 a, float4 b) {
    return a.x * b.x + a.y * b.y + a.z * b.z + a.w * b.w;
}

// Block reduction (256 threads) -> result valid on thread 0.
__device__ __forceinline__ float block_reduce_256(float v) {
    __shared__ float sp[8];
    int lane = threadIdx.x & 31, wid = threadIdx.x >> 5;
    #pragma unroll
    for (int o = 16; o; o >>= 1) v += __shfl_down_sync(0xffffffffu, v, o);
    if (lane == 0) sp[wid] = v;
    __syncthreads();
    if (threadIdx.x < 32) {
        v = (lane < 8) ? sp[lane] : 0.0f;
        #pragma unroll
        for (int o = 4; o; o >>= 1) v += __shfl_down_sync(0xffffffffu, v, o);
    }
    return v;
}

// Warp-aggregated histogram add (conflict-free for hot bins).
__device__ __forceinline__ void hist_add(unsigned* s_hist, int bin, bool pred) {
    unsigned active = __ballot_sync(0xffffffffu, pred);
    if (pred) {
        unsigned mask = __match_any_sync(active, bin);
        int leader = __ffs(mask) - 1;
        if ((int)(threadIdx.x & 31) == leader)
            atomicAdd(&s_hist[bin], (unsigned)__popc(mask));
    }
}

// Warp 0 locates the bin holding the k-th largest in a 256-bin histogram.
__device__ __forceinline__ void find_bin_warp0(const unsigned* s_hist, int k,
                                               int* s_bin, int* s_k) {
    if (threadIdx.x < 32) {
        int lane = threadIdx.x;
        unsigned b[8]; unsigned tot = 0;
        #pragma unroll
        for (int j = 0; j < 8; j++) { b[j] = s_hist[lane * 8 + j]; tot += b[j]; }
        unsigned suf = tot;
        #pragma unroll
        for (int o = 1; o < 32; o <<= 1) {
            unsigned n = __shfl_down_sync(0xffffffffu, suf, o);
            if (lane + o < 32) suf += n;
        }
        unsigned above = suf - tot;
        unsigned ge[8]; unsigned run = above;
        #pragma unroll
        for (int j = 7; j >= 0; j--) { run += b[j]; ge[j] = run; }
        unsigned gt = above;
        #pragma unroll
        for (int j = 7; j >= 0; j--) {
            if (ge[j] >= (unsigned)k && gt < (unsigned)k) {
                *s_bin = lane * 8 + j;
                *s_k   = k - (int)gt;
            }
            gt = ge[j];
        }
    }
}

// Exact K-th largest via candidate compaction (pass 1 full, passes 2-4 over
// the ~candidates sharing the selected top byte). Fallback: full passes.
template<int M>
__device__ float kth_select(const unsigned* uv, int K) {
    __shared__ unsigned s_hist[256];
    __shared__ unsigned s_cand[2048];
    __shared__ int s_bin, s_k, s_cnt;
    if (threadIdx.x < 256) s_hist[threadIdx.x] = 0;
    __syncthreads();
    #pragma unroll
    for (int j = 0; j < M; j++) hist_add(s_hist, uv[j] >> 24, true);
    __syncthreads();
    find_bin_warp0(s_hist, K, &s_bin, &s_k);
    __syncthreads();
    unsigned b0 = (unsigned)s_bin;
    int k = s_k;
    unsigned prefix = b0 << 24;
    if (threadIdx.x == 0) s_cnt = 0;
    __syncthreads();
    #pragma unroll
    for (int j = 0; j < M; j++) {
        if ((uv[j] >> 24) == b0) {
            int pos = atomicAdd(&s_cnt, 1);
            if (pos < 2048) s_cand[pos] = uv[j];
        }
    }
    __syncthreads();
    int cnt = s_cnt;
    if (cnt <= 2048) {
        #pragma unroll
        for (int shift = 16; shift >= 0; shift -= 8) {
            unsigned hi = 0xFFFFFFFFu << (shift + 8);
            if (threadIdx.x < 256) s_hist[threadIdx.x] = 0;
            __syncthreads();
            for (int i = threadIdx.x; i < cnt; i += blockDim.x) {
                unsigned u = s_cand[i];
                if ((u & hi) == prefix) atomicAdd(&s_hist[(u >> shift) & 255], 1u);
            }
            __syncthreads();
            find_bin_warp0(s_hist, k, &s_bin, &s_k);
            __syncthreads();
            prefix |= ((unsigned)s_bin) << shift;
            k = s_k;
            __syncthreads();
        }
        return u2f(prefix);
    }
    #pragma unroll
    for (int shift = 16; shift >= 0; shift -= 8) {
        unsigned hi = 0xFFFFFFFFu << (shift + 8);
        if (threadIdx.x < 256) s_hist[threadIdx.x] = 0;
        __syncthreads();
        #pragma unroll
        for (int j = 0; j < M; j++) {
            unsigned u = uv[j];
            hist_add(s_hist, (u >> shift) & 255, (u & hi) == prefix);
        }
        __syncthreads();
        find_bin_warp0(s_hist, k, &s_bin, &s_k);
        __syncthreads();
        prefix |= ((unsigned)s_bin) << shift;
        k = s_k;
        __syncthreads();
    }
    return u2f(prefix);
}

// ---------------- K1: dual matvec, HALF-row per block (grid 32768) --------------------
// update_W-shaped grid: 256 threads x 2 front-batched float4 W loads (8 KB/block).
// Partials stored to g_hp0 / g_hp1 (no atomics; deterministic 2-term sum later).
__global__ __launch_bounds__(256) void matvec_dual_kernel(
        const float* __restrict__ Wa, const float* __restrict__ Wb,
        const float* __restrict__ x) {
    int cr   = blockIdx.x >> 1;         // combined row index
    int half = blockIdx.x & 1;
    const float* W; int r;
    if (cr < DIM_CA3) { W = Wa; r = cr; }
    else              { W = Wb; r = cr - DIM_CA3; }
    const float4* w4 = reinterpret_cast<const float4*>(W) + (size_t)r * (DIM_EI / 4)
                       + half * (DIM_EI / 8);
    const float4* x4 = reinterpret_cast<const float4*>(x) + half * (DIM_EI / 8);
    int t = threadIdx.x;
    float4 a0 = __ldcs(&w4[t]);
    float4 a1 = __ldcs(&w4[t + 256]);
    float4 b0 = __ldg(&x4[t]);
    float4 b1 = __ldg(&x4[t + 256]);
    float acc = dot4(a0, b0) + dot4(a1, b1);
    float sum = block_reduce_256(acc);
    if (threadIdx.x == 0) {
        if (half) g_hp1[cr] = sum; else g_hp0[cr] = sum;
    }
}

// ---------------- K2: block0 -> top-2(h1)+x_ca3+compaction; block1 -> top-100(h3)+IS ----
__global__ void stageA_kernel() {
    __shared__ int wsum[32];
    int lane = threadIdx.x & 31, wid = threadIdx.x >> 5;
    int base = threadIdx.x * 8;
    int off0 = (blockIdx.x == 0) ? 0 : DIM_CA3;   // combined-row offset
    int K = (blockIdx.x == 0) ? 2 : 100;

    float xv[8]; unsigned uv[8];
    #pragma unroll
    for (int j = 0; j < 8; j++) {
        int cr = off0 + base + j;
        xv[j] = g_hp0[cr] + g_hp1[cr];
        uv[j] = f2u(xv[j]);
    }
    float th = kth_select<8>(uv, K);

    if (blockIdx.x == 0) {
        float vals[8]; int keep[8]; int cnt = 0;
        #pragma unroll
        for (int j = 0; j < 8; j++) {
            int kp = (xv[j] >= th);
            float v = kp ? sigm(BETA * (xv[j] - th)) : 0.0f;
            g_xca3[base + j] = v;
            vals[j] = v; keep[j] = kp; cnt += kp;
        }
        int incl = cnt;
        #pragma unroll
        for (int o = 1; o < 32; o <<= 1) {
            int n = __shfl_up_sync(0xffffffffu, incl, o);
            if (lane >= o) incl += n;
        }
        if (lane == 31) wsum[wid] = incl;
        __syncthreads();
        if (threadIdx.x == 0) {
            int s = 0;
            #pragma unroll
            for (int i = 0; i < 32; i++) { int c = wsum[i]; wsum[i] = s; s += c; }
            g_nnz_cnt = s;
            g_ctr = 0;
        }
        __syncthreads();
        int off = wsum[wid] + incl - cnt;
        #pragma unroll
        for (int j = 0; j < 8; j++) {
            if (keep[j]) { g_nnz_idx[off] = base + j; g_nnz_val[off] = vals[j]; ++off; }
        }
    } else {
        #pragma unroll
        for (int j = 0; j < 8; j++)
            g_IS[base + j] = (xv[j] >= th) ? sigm(BETA * (xv[j] - th)) : 0.0f;
    }
}

// ---------------- K3: fused h2 gather (x_ca3 ~2 nnz) + top-100 + dense sigmoid ----------
__global__ void stageBC_kernel(const float* __restrict__ W3) {
    int cnt = g_nnz_cnt;
    int base = threadIdx.x * 8;
    float hv[8]; unsigned uv[8];
    #pragma unroll
    for (int r = 0; r < 8; r++) {
        size_t rowoff = (size_t)(base + r) * DIM_CA3;
        float acc = 0.0f;
        for (int k = 0; k < cnt; k++)
            acc += W3[rowoff + g_nnz_idx[k]] * g_nnz_val[k];
        hv[r] = acc; uv[r] = f2u(acc);
    }
    float th = kth_select<8>(uv, 100);
    #pragma unroll
    for (int r = 0; r < 8; r++)
        g_xca1[base + r] = sigm(BETA * (hv[r] - th));   // flag=False: no hard mask
}

// ---------------- K4: W_new = (1-IS*a)*W + a*IS*x_ca3^T (32B per thread) --------------
__global__ void update_W_kernel(const float* __restrict__ W, float* __restrict__ out) {
    size_t idx = ((size_t)blockIdx.x * blockDim.x + threadIdx.x) * 8;
    int row = (int)(idx >> 13);
    int col = (int)(idx & (DIM_CA3 - 1));
    float s = g_IS[row];
    float a = 1.0f - s * ALPHA;
    float b = ALPHA * s;
    float4 w0 = __ldcs(reinterpret_cast<const float4*>(W + idx));
    float4 w1 = __ldcs(reinterpret_cast<const float4*>(W + idx + 4));
    float4 x0 = *reinterpret_cast<const float4*>(g_xca3 + col);
    float4 x1 = *reinterpret_cast<const float4*>(g_xca3 + col + 4);
    float4 o0, o1;
    o0.x = a * w0.x + b * x0.x;  o0.y = a * w0.y + b * x0.y;
    o0.z = a * w0.z + b * x0.z;  o0.w = a * w0.w + b * x0.w;
    o1.x = a * w1.x + b * x1.x;  o1.y = a * w1.y + b * x1.y;
    o1.z = a * w1.z + b * x1.z;  o1.w = a * w1.w + b * x1.w;
    __stcs(reinterpret_cast<float4*>(out + idx), o0);
    __stcs(reinterpret_cast<float4*>(out + idx + 4), o1);
}

// ---------------- K5: matvec_out BLOCK-per-row (grid 4096) + fused top-50 tail --------
__global__ __launch_bounds__(256) void matvec_out_kernel(
        const float* __restrict__ W, float* __restrict__ out) {
    int r = blockIdx.x;
    int tid = threadIdx.x;
    const float4* w4 = reinterpret_cast<const float4*>(W) + (size_t)r * (DIM_CA1 / 4);
    const float4* x4 = reinterpret_cast<const float4*>(g_xca1);
    float acc = 0.0f;
    float4 a0 = __ldcs(&w4[tid]);
    float4 a1 = __ldcs(&w4[tid + 256]);
    float4 a2 = __ldcs(&w4[tid + 512]);
    float4 a3 = __ldcs(&w4[tid + 768]);
    float4 a4 = __ldcs(&w4[tid + 1024]);
    float4 a5 = __ldcs(&w4[tid + 1280]);
    float4 a6 = __ldcs(&w4[tid + 1536]);
    float4 a7 = __ldcs(&w4[tid + 1792]);
    acc += dot4(a0, __ldg(&x4[tid]));
    acc += dot4(a1, __ldg(&x4[tid + 256]));
    acc += dot4(a2, __ldg(&x4[tid + 512]));
    acc += dot4(a3, __ldg(&x4[tid + 768]));
    acc += dot4(a4, __ldg(&x4[tid + 1024]));
    acc += dot4(a5, __ldg(&x4[tid + 1280]));
    acc += dot4(a6, __ldg(&x4[tid + 1536]));
    acc += dot4(a7, __ldg(&x4[tid + 1792]));
    float sum = block_reduce_256(acc);
    if (tid == 0) {
        g_h4[r] = sum;
        __threadfence();
    }
    __syncthreads();
    __shared__ bool s_last;
    if (tid == 0) {
        unsigned t = atomicAdd(&g_ctr, 1u);
        s_last = (t == gridDim.x - 1);
    }
    __syncthreads();
    if (!s_last) return;
    __threadfence();
    unsigned uv[16];
    #pragma unroll
    for (int j = 0; j < 16; j++) uv[j] = f2u(g_h4[tid * 16 + j]);
    float th = kth_select<16>(uv, 50);
    for (int i = tid; i < DIM_EO; i += 256) {
        float xx = g_h4[i];
        out[i] = (xx >= th) ? sigm(BETA * (xx - th)) : 0.0f;
    }
}

// ---------------- launch: R13 fork-join structure ----------------
extern "C" void kernel_launch(void* const* d_in, const int* in_sizes, int n_in,
                              void* d_out, int out_size) {
    const float* x_ei      = (const float*)d_in[0];
    const float* W_ei_ca3  = (const float*)d_in[1];
    const float* W_ei_ca1  = (const float*)d_in[2];
    const float* W_ca3_ca1 = (const float*)d_in[3];
    const float* W_ca1_eo  = (const float*)d_in[4];
    float* out = (float*)d_out;

    cudaStream_t s1;
    cudaStreamCreateWithFlags(&s1, cudaStreamNonBlocking);
    cudaEvent_t e_fork, e_join;
    cudaEventCreateWithFlags(&e_fork, cudaEventDisableTiming);
    cudaEventCreateWithFlags(&e_join, cudaEventDisableTiming);

    matvec_dual_kernel<<<NROWS * 2, 256>>>(W_ei_ca3, W_ei_ca1, x_ei);
    stageA_kernel<<<2, 1024>>>();

    // fork: B-chain on s1, concurrent with update_W on stream0
    cudaEventRecord(e_fork, 0);
    cudaStreamWaitEvent(s1, e_fork, 0);

    stageBC_kernel<<<1, 1024, 0, s1>>>(W_ca3_ca1);
    matvec_out_kernel<<<DIM_EO, 256, 0, s1>>>(W_ca1_eo, out);

    update_W_kernel<<<(unsigned)((size_t)DIM_CA1 * DIM_CA3 / 8 / 256), 256>>>(W_ca3_ca1, out + DIM_EO);

    // join
    cudaEventRecord(e_join, s1);
    cudaStreamWaitEvent(0, e_join, 0);

    cudaEventDestroy(e_fork);
    cudaEventDestroy(e_join);
    cudaStreamDestroy(s1);
}

// round 17
// speedup vs baseline: 1.0562x; 1.0110x over previous
#include <cuda_runtime.h>
#include <math.h>

#define DIM_EI  4096
#define DIM_CA3 8192
#define DIM_CA1 8192
#define DIM_EO  4096

static constexpr float BETA  = 10.0f;
static constexpr float ALPHA = 0.01f;

// ---------------- device scratch ----------------
__device__ float g_h1[DIM_CA3];
__device__ float g_h3[DIM_CA1];
__device__ float g_h4[DIM_EO];
__device__ float g_xca3[DIM_CA3];
__device__ float g_IS[DIM_CA1];
__device__ float g_xca1[DIM_CA1];
__device__ int   g_nnz_idx[DIM_CA3];
__device__ float g_nnz_val[DIM_CA3];
__device__ int   g_nnz_cnt;
__device__ unsigned g_ctr;

// ---------------- helpers ----------------
__device__ __forceinline__ unsigned f2u(float f) {
    unsigned u = __float_as_uint(f);
    return (u & 0x80000000u) ? ~u : (u | 0x80000000u);
}
__device__ __forceinline__ float u2f(unsigned u) {
    return __uint_as_float((u & 0x80000000u) ? (u & 0x7fffffffu) : ~u);
}
__device__ __forceinline__ float sigm(float z) { return 1.0f / (1.0f + expf(-z)); }
__device__ __forceinline__ float dot4(float4 a, float4 b) {
    return a.x * b.x + a.y * b.y + a.z * b.z + a.w * b.w;
}

// Block reduction (256 threads) -> result valid on thread 0.
__device__ __forceinline__ float block_reduce_256(float v) {
    __shared__ float sp[8];
    int lane = threadIdx.x & 31, wid = threadIdx.x >> 5;
    #pragma unroll
    for (int o = 16; o; o >>= 1) v += __shfl_down_sync(0xffffffffu, v, o);
    if (lane == 0) sp[wid] = v;
    __syncthreads();
    if (threadIdx.x < 32) {
        v = (lane < 8) ? sp[lane] : 0.0f;
        #pragma unroll
        for (int o = 4; o; o >>= 1) v += __shfl_down_sync(0xffffffffu, v, o);
    }
    return v;
}

// Warp-aggregated histogram add (conflict-free for hot bins).
__device__ __forceinline__ void hist_add(unsigned* s_hist, int bin, bool pred) {
    unsigned active = __ballot_sync(0xffffffffu, pred);
    if (pred) {
        unsigned mask = __match_any_sync(active, bin);
        int leader = __ffs(mask) - 1;
        if ((int)(threadIdx.x & 31) == leader)
            atomicAdd(&s_hist[bin], (unsigned)__popc(mask));
    }
}

// Warp 0 locates the bin holding the k-th largest in a 256-bin histogram.
__device__ __forceinline__ void find_bin_warp0(const unsigned* s_hist, int k,
                                               int* s_bin, int* s_k) {
    if (threadIdx.x < 32) {
        int lane = threadIdx.x;
        unsigned b[8]; unsigned tot = 0;
        #pragma unroll
        for (int j = 0; j < 8; j++) { b[j] = s_hist[lane * 8 + j]; tot += b[j]; }
        unsigned suf = tot;
        #pragma unroll
        for (int o = 1; o < 32; o <<= 1) {
            unsigned n = __shfl_down_sync(0xffffffffu, suf, o);
            if (lane + o < 32) suf += n;
        }
        unsigned above = suf - tot;
        unsigned ge[8]; unsigned run = above;
        #pragma unroll
        for (int j = 7; j >= 0; j--) { run += b[j]; ge[j] = run; }
        unsigned gt = above;
        #pragma unroll
        for (int j = 7; j >= 0; j--) {
            if (ge[j] >= (unsigned)k && gt < (unsigned)k) {
                *s_bin = lane * 8 + j;
                *s_k   = k - (int)gt;
            }
            gt = ge[j];
        }
    }
}

// Exact K-th largest via candidate compaction (pass 1 full, passes 2-4 over
// the ~candidates sharing the selected top byte). Fallback: full passes.
template<int M>
__device__ float kth_select(const unsigned* uv, int K) {
    __shared__ unsigned s_hist[256];
    __shared__ unsigned s_cand[2048];
    __shared__ int s_bin, s_k, s_cnt;
    if (threadIdx.x < 256) s_hist[threadIdx.x] = 0;
    __syncthreads();
    #pragma unroll
    for (int j = 0; j < M; j++) hist_add(s_hist, uv[j] >> 24, true);
    __syncthreads();
    find_bin_warp0(s_hist, K, &s_bin, &s_k);
    __syncthreads();
    unsigned b0 = (unsigned)s_bin;
    int k = s_k;
    unsigned prefix = b0 << 24;
    if (threadIdx.x == 0) s_cnt = 0;
    __syncthreads();
    #pragma unroll
    for (int j = 0; j < M; j++) {
        if ((uv[j] >> 24) == b0) {
            int pos = atomicAdd(&s_cnt, 1);
            if (pos < 2048) s_cand[pos] = uv[j];
        }
    }
    __syncthreads();
    int cnt = s_cnt;
    if (cnt <= 2048) {
        #pragma unroll
        for (int shift = 16; shift >= 0; shift -= 8) {
            unsigned hi = 0xFFFFFFFFu << (shift + 8);
            if (threadIdx.x < 256) s_hist[threadIdx.x] = 0;
            __syncthreads();
            for (int i = threadIdx.x; i < cnt; i += blockDim.x) {
                unsigned u = s_cand[i];
                if ((u & hi) == prefix) atomicAdd(&s_hist[(u >> shift) & 255], 1u);
            }
            __syncthreads();
            find_bin_warp0(s_hist, k, &s_bin, &s_k);
            __syncthreads();
            prefix |= ((unsigned)s_bin) << shift;
            k = s_k;
            __syncthreads();
        }
        return u2f(prefix);
    }
    #pragma unroll
    for (int shift = 16; shift >= 0; shift -= 8) {
        unsigned hi = 0xFFFFFFFFu << (shift + 8);
        if (threadIdx.x < 256) s_hist[threadIdx.x] = 0;
        __syncthreads();
        #pragma unroll
        for (int j = 0; j < M; j++) {
            unsigned u = uv[j];
            hist_add(s_hist, (u >> shift) & 255, (u & hi) == prefix);
        }
        __syncthreads();
        find_bin_warp0(s_hist, k, &s_bin, &s_k);
        __syncthreads();
        prefix |= ((unsigned)s_bin) << shift;
        k = s_k;
        __syncthreads();
    }
    return u2f(prefix);
}

// ---------------- K1: dual matvec, BLOCK-per-row (grid 16384, R13 winner) -------------
// Each block triggers PDL completion after storing its row result.
__global__ __launch_bounds__(256) void matvec_dual_kernel(
        const float* __restrict__ Wa, const float* __restrict__ Wb,
        const float* __restrict__ x) {
    int r = blockIdx.x;
    const float* W; float* out;
    if (r < DIM_CA3) { W = Wa; out = g_h1; }
    else             { W = Wb; out = g_h3; r -= DIM_CA3; }
    const float4* w4 = reinterpret_cast<const float4*>(W) + (size_t)r * (DIM_EI / 4);
    const float4* x4 = reinterpret_cast<const float4*>(x);
    int t = threadIdx.x;
    float4 a0 = __ldcs(&w4[t]);
    float4 a1 = __ldcs(&w4[t + 256]);
    float4 a2 = __ldcs(&w4[t + 512]);
    float4 a3 = __ldcs(&w4[t + 768]);
    float4 b0 = __ldg(&x4[t]);
    float4 b1 = __ldg(&x4[t + 256]);
    float4 b2 = __ldg(&x4[t + 512]);
    float4 b3 = __ldg(&x4[t + 768]);
    float acc = dot4(a0, b0) + dot4(a1, b1) + dot4(a2, b2) + dot4(a3, b3);
    float sum = block_reduce_256(acc);
    if (threadIdx.x == 0) {
        out[r] = sum;
        __threadfence();
        cudaTriggerProgrammaticLaunchCompletion();
    }
}

// ---------------- K2: block0 -> top-2(h1)+x_ca3+compaction; block1 -> top-100(h3)+IS ----
// Launched with PDL: prologue overlaps mv_dual's tail; data gated by grid-dep sync.
__global__ void stageA_kernel() {
    cudaGridDependencySynchronize();
    __shared__ int wsum[32];
    int lane = threadIdx.x & 31, wid = threadIdx.x >> 5;
    int base = threadIdx.x * 8;
    if (blockIdx.x == 0) {
        float xv[8]; unsigned uv[8];
        #pragma unroll
        for (int j = 0; j < 8; j++) { xv[j] = g_h1[base + j]; uv[j] = f2u(xv[j]); }
        float th = kth_select<8>(uv, 2);
        float vals[8]; int keep[8]; int cnt = 0;
        #pragma unroll
        for (int j = 0; j < 8; j++) {
            int kp = (xv[j] >= th);
            float v = kp ? sigm(BETA * (xv[j] - th)) : 0.0f;
            g_xca3[base + j] = v;
            vals[j] = v; keep[j] = kp; cnt += kp;
        }
        int incl = cnt;
        #pragma unroll
        for (int o = 1; o < 32; o <<= 1) {
            int n = __shfl_up_sync(0xffffffffu, incl, o);
            if (lane >= o) incl += n;
        }
        if (lane == 31) wsum[wid] = incl;
        __syncthreads();
        if (threadIdx.x == 0) {
            int s = 0;
            #pragma unroll
            for (int i = 0; i < 32; i++) { int c = wsum[i]; wsum[i] = s; s += c; }
            g_nnz_cnt = s;
            g_ctr = 0;
        }
        __syncthreads();
        int off = wsum[wid] + incl - cnt;
        #pragma unroll
        for (int j = 0; j < 8; j++) {
            if (keep[j]) { g_nnz_idx[off] = base + j; g_nnz_val[off] = vals[j]; ++off; }
        }
    } else {
        float xv[8]; unsigned uv[8];
        #pragma unroll
        for (int j = 0; j < 8; j++) { xv[j] = g_h3[base + j]; uv[j] = f2u(xv[j]); }
        float th = kth_select<8>(uv, 100);
        #pragma unroll
        for (int j = 0; j < 8; j++)
            g_IS[base + j] = (xv[j] >= th) ? sigm(BETA * (xv[j] - th)) : 0.0f;
    }
}

// ---------------- K3: fused h2 gather (x_ca3 ~2 nnz) + top-100 + dense sigmoid ----------
__global__ void stageBC_kernel(const float* __restrict__ W3) {
    int cnt = g_nnz_cnt;
    int base = threadIdx.x * 8;
    float hv[8]; unsigned uv[8];
    #pragma unroll
    for (int r = 0; r < 8; r++) {
        size_t rowoff = (size_t)(base + r) * DIM_CA3;
        float acc = 0.0f;
        for (int k = 0; k < cnt; k++)
            acc += W3[rowoff + g_nnz_idx[k]] * g_nnz_val[k];
        hv[r] = acc; uv[r] = f2u(acc);
    }
    float th = kth_select<8>(uv, 100);
    #pragma unroll
    for (int r = 0; r < 8; r++)
        g_xca1[base + r] = sigm(BETA * (hv[r] - th));   // flag=False: no hard mask
}

// ---------------- K4: W_new = (1-IS*a)*W + a*IS*x_ca3^T (32B per thread) --------------
__global__ void update_W_kernel(const float* __restrict__ W, float* __restrict__ out) {
    size_t idx = ((size_t)blockIdx.x * blockDim.x + threadIdx.x) * 8;
    int row = (int)(idx >> 13);
    int col = (int)(idx & (DIM_CA3 - 1));
    float s = g_IS[row];
    float a = 1.0f - s * ALPHA;
    float b = ALPHA * s;
    float4 w0 = __ldcs(reinterpret_cast<const float4*>(W + idx));
    float4 w1 = __ldcs(reinterpret_cast<const float4*>(W + idx + 4));
    float4 x0 = *reinterpret_cast<const float4*>(g_xca3 + col);
    float4 x1 = *reinterpret_cast<const float4*>(g_xca3 + col + 4);
    float4 o0, o1;
    o0.x = a * w0.x + b * x0.x;  o0.y = a * w0.y + b * x0.y;
    o0.z = a * w0.z + b * x0.z;  o0.w = a * w0.w + b * x0.w;
    o1.x = a * w1.x + b * x1.x;  o1.y = a * w1.y + b * x1.y;
    o1.z = a * w1.z + b * x1.z;  o1.w = a * w1.w + b * x1.w;
    __stcs(reinterpret_cast<float4*>(out + idx), o0);
    __stcs(reinterpret_cast<float4*>(out + idx + 4), o1);
}

// ---------------- K5: matvec_out BLOCK-per-row (grid 4096) + fused top-50 tail --------
__global__ __launch_bounds__(256) void matvec_out_kernel(
        const float* __restrict__ W, float* __restrict__ out) {
    int r = blockIdx.x;
    int tid = threadIdx.x;
    const float4* w4 = reinterpret_cast<const float4*>(W) + (size_t)r * (DIM_CA1 / 4);
    const float4* x4 = reinterpret_cast<const float4*>(g_xca1);
    float acc = 0.0f;
    float4 a0 = __ldcs(&w4[tid]);
    float4 a1 = __ldcs(&w4[tid + 256]);
    float4 a2 = __ldcs(&w4[tid + 512]);
    float4 a3 = __ldcs(&w4[tid + 768]);
    float4 a4 = __ldcs(&w4[tid + 1024]);
    float4 a5 = __ldcs(&w4[tid + 1280]);
    float4 a6 = __ldcs(&w4[tid + 1536]);
    float4 a7 = __ldcs(&w4[tid + 1792]);
    acc += dot4(a0, __ldg(&x4[tid]));
    acc += dot4(a1, __ldg(&x4[tid + 256]));
    acc += dot4(a2, __ldg(&x4[tid + 512]));
    acc += dot4(a3, __ldg(&x4[tid + 768]));
    acc += dot4(a4, __ldg(&x4[tid + 1024]));
    acc += dot4(a5, __ldg(&x4[tid + 1280]));
    acc += dot4(a6, __ldg(&x4[tid + 1536]));
    acc += dot4(a7, __ldg(&x4[tid + 1792]));
    float sum = block_reduce_256(acc);
    if (tid == 0) {
        g_h4[r] = sum;
        __threadfence();
    }
    __syncthreads();
    __shared__ bool s_last;
    if (tid == 0) {
        unsigned t = atomicAdd(&g_ctr, 1u);
        s_last = (t == gridDim.x - 1);
    }
    __syncthreads();
    if (!s_last) return;
    __threadfence();
    unsigned uv[16];
    #pragma unroll
    for (int j = 0; j < 16; j++) uv[j] = f2u(g_h4[tid * 16 + j]);
    float th = kth_select<16>(uv, 50);
    for (int i = tid; i < DIM_EO; i += 256) {
        float xx = g_h4[i];
        out[i] = (xx >= th) ? sigm(BETA * (xx - th)) : 0.0f;
    }
}

// ---------------- launch: R13 fork-join + PDL on mv_dual -> stageA --------------------
extern "C" void kernel_launch(void* const* d_in, const int* in_sizes, int n_in,
                              void* d_out, int out_size) {
    const float* x_ei      = (const float*)d_in[0];
    const float* W_ei_ca3  = (const float*)d_in[1];
    const float* W_ei_ca1  = (const float*)d_in[2];
    const float* W_ca3_ca1 = (const float*)d_in[3];
    const float* W_ca1_eo  = (const float*)d_in[4];
    float* out = (float*)d_out;

    cudaStream_t s1;
    cudaStreamCreateWithFlags(&s1, cudaStreamNonBlocking);
    cudaEvent_t e_fork, e_join;
    cudaEventCreateWithFlags(&e_fork, cudaEventDisableTiming);
    cudaEventCreateWithFlags(&e_join, cudaEventDisableTiming);

    matvec_dual_kernel<<<DIM_CA3 + DIM_CA1, 256>>>(W_ei_ca3, W_ei_ca1, x_ei);

    // stageA with programmatic dependent launch (overlaps mv_dual tail)
    {
        cudaLaunchConfig_t cfg = {};
        cfg.gridDim  = dim3(2, 1, 1);
        cfg.blockDim = dim3(1024, 1, 1);
        cfg.stream   = 0;
        cudaLaunchAttribute attr[1];
        attr[0].id = cudaLaunchAttributeProgrammaticStreamSerialization;
        attr[0].val.programmaticStreamSerializationAllowed = 1;
        cfg.attrs = attr;
        cfg.numAttrs = 1;
        cudaLaunchKernelEx(&cfg, stageA_kernel);
    }

    // fork: B-chain on s1, concurrent with update_W on stream0
    cudaEventRecord(e_fork, 0);
    cudaStreamWaitEvent(s1, e_fork, 0);

    stageBC_kernel<<<1, 1024, 0, s1>>>(W_ca3_ca1);
    matvec_out_kernel<<<DIM_EO, 256, 0, s1>>>(W_ca1_eo, out);

    update_W_kernel<<<(unsigned)((size_t)DIM_CA1 * DIM_CA3 / 8 / 256), 256>>>(W_ca3_ca1, out + DIM_EO);

    // join
    cudaEventRecord(e_join, s1);
    cudaStreamWaitEvent(0, e_join, 0);

    cudaEventDestroy(e_fork);
    cudaEventDestroy(e_join);
    cudaStreamDestroy(s1);
}